// round 1
// baseline (speedup 1.0000x reference)
#include <cuda_runtime.h>
#include <math.h>

#define D 128
#define HH 8
#define OO 16
#define NEG 0.2f
#define LNEPS 1e-5f

#define MAXN 50176
#define MAXE 800256

// ---------------- scratch (static device allocations; no cudaMalloc) -------
__device__ float g_xl[(size_t)MAXN * D];
__device__ float g_xr[(size_t)MAXN * D];
__device__ float g_logits[(size_t)MAXE * HH];
__device__ float g_agg[(size_t)MAXN * D];
__device__ float g_h[(size_t)MAXN * D];
__device__ float g_ffn1[(size_t)MAXN * 4 * D];
__device__ float g_f2[(size_t)MAXN * D];
__device__ int   g_deg[MAXN];
__device__ int   g_rowptr[MAXN + 1];
__device__ int   g_cursor[MAXN];
__device__ int   g_bsum[256];
__device__ int   g_eid[MAXE];
__device__ int   g_srcp[MAXE];

// ---------------- CSR build ------------------------------------------------
__global__ void k_zero_deg(int* deg, int N) {
    int i = blockIdx.x * blockDim.x + threadIdx.x;
    if (i < N) deg[i] = 0;
}

__global__ void k_count(const int* __restrict__ dst, int* deg, int E) {
    int e = blockIdx.x * blockDim.x + threadIdx.x;
    if (e < E) atomicAdd(&deg[dst[e]], 1);
}

// inclusive block scan of deg into rowptr[i+1] (per-block, no global offset)
__global__ void k_scan1(const int* __restrict__ deg, int* rowptr, int* bsum, int N) {
    __shared__ int sh[1024];
    int t = threadIdx.x;
    int i = blockIdx.x * 1024 + t;
    int v = (i < N) ? deg[i] : 0;
    sh[t] = v;
    __syncthreads();
    for (int off = 1; off < 1024; off <<= 1) {
        int add = (t >= off) ? sh[t - off] : 0;
        __syncthreads();
        sh[t] += add;
        __syncthreads();
    }
    if (i < N) rowptr[i + 1] = sh[t];
    if (t == 1023) bsum[blockIdx.x] = sh[1023];
}

__global__ void k_scan2(int* bsum, int nb) {
    if (threadIdx.x == 0 && blockIdx.x == 0) {
        int run = 0;
        for (int b = 0; b < nb; b++) { int v = bsum[b]; bsum[b] = run; run += v; }
    }
}

__global__ void k_scan3(const int* __restrict__ deg, int* rowptr, int* cursor,
                        const int* __restrict__ bsum, int N) {
    int t = threadIdx.x;
    int i = blockIdx.x * 1024 + t;
    if (i < N) {
        int v = rowptr[i + 1] + bsum[blockIdx.x];
        rowptr[i + 1] = v;
        cursor[i] = v - deg[i];
    }
    if (i == 0) rowptr[0] = 0;
}

__global__ void k_fill(const int* __restrict__ src, const int* __restrict__ dst,
                       int* cursor, int* eid, int* srcp, int E) {
    int e = blockIdx.x * blockDim.x + threadIdx.x;
    if (e < E) {
        int d = dst[e];
        int p = atomicAdd(&cursor[d], 1);
        eid[p]  = e;
        srcp[p] = src[e];
    }
}

// ---------------- generic SGEMM: C = act(A[M,K] @ B[K,Nc] + bias) ----------
// BM=BN=128, BK=16, 256 threads, 8x8 per thread.
__global__ void __launch_bounds__(256) sgemm_kernel(
    const float* __restrict__ A, const float* __restrict__ B,
    const float* __restrict__ bias, float* __restrict__ C,
    int M, int Nc, int K, int act)
{
    __shared__ float As[16][132];   // k-major (transposed), padded
    __shared__ float Bs[16][128];
    int t  = threadIdx.x;
    int tx = t & 15, ty = t >> 4;
    int m0 = blockIdx.y * 128, n0 = blockIdx.x * 128;

    float acc[8][8];
#pragma unroll
    for (int i = 0; i < 8; i++)
#pragma unroll
        for (int j = 0; j < 8; j++) acc[i][j] = 0.f;

    for (int k0 = 0; k0 < K; k0 += 16) {
#pragma unroll
        for (int i = 0; i < 2; i++) {
            int id  = t + i * 256;       // 512 float4 of A tile
            int row = id >> 2;
            int kq  = id & 3;
            float4 v = make_float4(0.f, 0.f, 0.f, 0.f);
            int gm = m0 + row;
            if (gm < M) v = *(const float4*)&A[(size_t)gm * K + k0 + kq * 4];
            As[kq * 4 + 0][row] = v.x;
            As[kq * 4 + 1][row] = v.y;
            As[kq * 4 + 2][row] = v.z;
            As[kq * 4 + 3][row] = v.w;
        }
#pragma unroll
        for (int i = 0; i < 2; i++) {
            int id = t + i * 256;        // 512 float4 of B tile
            int kk = id >> 5;
            int cq = id & 31;
            *(float4*)&Bs[kk][cq * 4] =
                *(const float4*)&B[(size_t)(k0 + kk) * Nc + n0 + cq * 4];
        }
        __syncthreads();
#pragma unroll
        for (int kk = 0; kk < 16; kk++) {
            float a[8], b[8];
            *(float4*)&a[0] = *(float4*)&As[kk][ty * 8];
            *(float4*)&a[4] = *(float4*)&As[kk][ty * 8 + 4];
            *(float4*)&b[0] = *(float4*)&Bs[kk][tx * 8];
            *(float4*)&b[4] = *(float4*)&Bs[kk][tx * 8 + 4];
#pragma unroll
            for (int i = 0; i < 8; i++)
#pragma unroll
                for (int j = 0; j < 8; j++) acc[i][j] += a[i] * b[j];
        }
        __syncthreads();
    }

    float bv[8];
    *(float4*)&bv[0] = *(const float4*)&bias[n0 + tx * 8];
    *(float4*)&bv[4] = *(const float4*)&bias[n0 + tx * 8 + 4];
#pragma unroll
    for (int i = 0; i < 8; i++) {
        int gm = m0 + ty * 8 + i;
        if (gm >= M) continue;
        float o[8];
#pragma unroll
        for (int j = 0; j < 8; j++) {
            float v = acc[i][j] + bv[j];
            if (act) v = 0.5f * v * (1.0f + erff(v * 0.70710678118654752f));
            o[j] = v;
        }
        *(float4*)&C[(size_t)gm * Nc + n0 + tx * 8]     = *(float4*)&o[0];
        *(float4*)&C[(size_t)gm * Nc + n0 + tx * 8 + 4] = *(float4*)&o[4];
    }
}

// ---------------- fused edge kernel: logits[e,h] ---------------------------
// Per CTA: 128 edges. ee = EA_tile @ W_e (128x128x128 GEMM, reg-tiled),
// then + xl[src] + xr[dst], leaky_relu, dot with att -> logits. Full ee
// never leaves the CTA.
#define EPB 128
__global__ void __launch_bounds__(256) edge_logits_kernel(
    const float* __restrict__ EA, const int* __restrict__ srcA,
    const int* __restrict__ dstA, const float* __restrict__ We,
    const float* __restrict__ att, const float* __restrict__ xl,
    const float* __restrict__ xr, float* __restrict__ logits, int E)
{
    extern __shared__ float es[];
    float* As   = es;                    // [128][136] k-major: As[k*136+e]
    float* Bs   = As + 128 * 136;        // [128][128]
    float* part = Bs + 128 * 128;        // [128][16]
    float* satt = part + 128 * 16;       // [128]
    int*  ssrc  = (int*)(satt + 128);    // [128]
    int*  sdst  = ssrc + 128;            // [128]

    int t  = threadIdx.x;
    int tx = t & 15, ty = t >> 4;
    int e0 = blockIdx.x * EPB;

    // load edge_attr tile transposed (k-major)
#pragma unroll
    for (int i = 0; i < 16; i++) {
        int id = t + i * 256;            // 4096 float4
        int e  = id >> 5;
        int kq = id & 31;
        float4 v = make_float4(0.f, 0.f, 0.f, 0.f);
        int ge = e0 + e;
        if (ge < E) v = *(const float4*)&EA[(size_t)ge * 128 + kq * 4];
        As[(kq * 4 + 0) * 136 + e] = v.x;
        As[(kq * 4 + 1) * 136 + e] = v.y;
        As[(kq * 4 + 2) * 136 + e] = v.z;
        As[(kq * 4 + 3) * 136 + e] = v.w;
    }
    // load W_e
#pragma unroll
    for (int i = 0; i < 16; i++) {
        int id = t + i * 256;
        int kk = id >> 5;
        int cq = id & 31;
        *(float4*)&Bs[kk * 128 + cq * 4] = *(const float4*)&We[kk * 128 + cq * 4];
    }
    if (t < 128) {
        satt[t] = att[t];
        int ge = e0 + t;
        if (ge >= E) ge = E - 1;
        ssrc[t] = srcA[ge];
        sdst[t] = dstA[ge];
    }
    __syncthreads();

    float acc[8][8];
#pragma unroll
    for (int i = 0; i < 8; i++)
#pragma unroll
        for (int j = 0; j < 8; j++) acc[i][j] = 0.f;

#pragma unroll 8
    for (int kk = 0; kk < 128; kk++) {
        float a[8], b[8];
        *(float4*)&a[0] = *(float4*)&As[kk * 136 + ty * 8];
        *(float4*)&a[4] = *(float4*)&As[kk * 136 + ty * 8 + 4];
        *(float4*)&b[0] = *(float4*)&Bs[kk * 128 + tx * 8];
        *(float4*)&b[4] = *(float4*)&Bs[kk * 128 + tx * 8 + 4];
#pragma unroll
        for (int i = 0; i < 8; i++)
#pragma unroll
            for (int j = 0; j < 8; j++) acc[i][j] += a[i] * b[j];
    }

    // epilogue: gather xl[src], xr[dst], leaky-relu, partial att-dot.
    // cols tx*8..tx*8+7 lie entirely inside head tx/2.
    int c0 = tx * 8;
    float attv[8];
    *(float4*)&attv[0] = *(float4*)&satt[c0];
    *(float4*)&attv[4] = *(float4*)&satt[c0 + 4];
#pragma unroll
    for (int i = 0; i < 8; i++) {
        int r  = ty * 8 + i;
        int ge = e0 + r;
        float p = 0.f;
        if (ge < E) {
            int s  = ssrc[r];
            int d2 = sdst[r];
            float xlv[8], xrv[8];
            *(float4*)&xlv[0] = *(const float4*)&xl[(size_t)s  * D + c0];
            *(float4*)&xlv[4] = *(const float4*)&xl[(size_t)s  * D + c0 + 4];
            *(float4*)&xrv[0] = *(const float4*)&xr[(size_t)d2 * D + c0];
            *(float4*)&xrv[4] = *(const float4*)&xr[(size_t)d2 * D + c0 + 4];
#pragma unroll
            for (int j = 0; j < 8; j++) {
                float v = acc[i][j] + xlv[j] + xrv[j];
                v = (v > 0.f) ? v : NEG * v;
                p += v * attv[j];
            }
        }
        part[r * 16 + tx] = p;
    }
    __syncthreads();
    for (int idx = t; idx < 128 * HH; idx += 256) {
        int e = idx >> 3, h = idx & 7;
        int ge = e0 + e;
        if (ge < E)
            logits[(size_t)ge * HH + h] = part[e * 16 + 2 * h] + part[e * 16 + 2 * h + 1];
    }
}

// ---------------- per-node softmax + aggregation (warp per node) -----------
__global__ void node_attn_kernel(const int* __restrict__ rowptr,
                                 const int* __restrict__ eid,
                                 const int* __restrict__ srcp,
                                 const float* __restrict__ logits,
                                 const float* __restrict__ xl,
                                 float* __restrict__ agg, int N)
{
    int wid  = (blockIdx.x * blockDim.x + threadIdx.x) >> 5;
    int lane = threadIdx.x & 31;
    if (wid >= N) return;
    int n   = wid;
    int beg = rowptr[n], end = rowptr[n + 1];

    int h = lane & 7, rep = lane >> 3;                 // 4 replicas per head
    float mx = -1e30f;
    for (int i = beg + rep; i < end; i += 4)
        mx = fmaxf(mx, logits[(size_t)eid[i] * HH + h]);
    mx = fmaxf(mx, __shfl_xor_sync(0xffffffffu, mx, 8));
    mx = fmaxf(mx, __shfl_xor_sync(0xffffffffu, mx, 16));
    float s = 0.f;
    for (int i = beg + rep; i < end; i += 4)
        s += expf(logits[(size_t)eid[i] * HH + h] - mx);
    s += __shfl_xor_sync(0xffffffffu, s, 8);
    s += __shfl_xor_sync(0xffffffffu, s, 16);
    float inv = 1.f / (s + 1e-16f);

    int h2 = lane >> 2;                                // head for aggregation
    float mxh  = __shfl_sync(0xffffffffu, mx,  h2);    // lanes 0..7 hold heads 0..7
    float invh = __shfl_sync(0xffffffffu, inv, h2);
    int off = lane * 4;                                // = h2*16 + (lane&3)*4

    float4 acc = make_float4(0.f, 0.f, 0.f, 0.f);
    for (int i = beg; i < end; i++) {
        int e  = eid[i];
        int sN = srcp[i];
        float a = expf(logits[(size_t)e * HH + h2] - mxh) * invh;
        float4 v = *(const float4*)&xl[(size_t)sN * D + off];
        acc.x += a * v.x; acc.y += a * v.y; acc.z += a * v.z; acc.w += a * v.w;
    }
    *(float4*)&agg[(size_t)n * D + off] = acc;
}

// ---------------- LayerNorm over D=128 (warp per row) ----------------------
__global__ void ln_kernel(const float* __restrict__ a, const float* __restrict__ b,
                          const float* __restrict__ extra_bias,
                          const float* __restrict__ g, const float* __restrict__ be,
                          float* __restrict__ out, int N, int has_extra)
{
    int wid  = (blockIdx.x * blockDim.x + threadIdx.x) >> 5;
    int lane = threadIdx.x & 31;
    if (wid >= N) return;
    int c = lane * 4;
    float4 va = *(const float4*)&a[(size_t)wid * D + c];
    float4 vb = *(const float4*)&b[(size_t)wid * D + c];
    float4 v = make_float4(va.x + vb.x, va.y + vb.y, va.z + vb.z, va.w + vb.w);
    if (has_extra) {
        float4 ex = *(const float4*)&extra_bias[c];
        v.x += ex.x; v.y += ex.y; v.z += ex.z; v.w += ex.w;
    }
    float s = v.x + v.y + v.z + v.w;
#pragma unroll
    for (int o = 1; o < 32; o <<= 1) s += __shfl_xor_sync(0xffffffffu, s, o);
    float mu = s * (1.f / 128.f);
    float dx = v.x - mu, dy = v.y - mu, dz = v.z - mu, dw = v.w - mu;
    float q = dx * dx + dy * dy + dz * dz + dw * dw;
#pragma unroll
    for (int o = 1; o < 32; o <<= 1) q += __shfl_xor_sync(0xffffffffu, q, o);
    float rs = rsqrtf(q * (1.f / 128.f) + LNEPS);
    float4 gg = *(const float4*)&g[c];
    float4 bb = *(const float4*)&be[c];
    float4 o4;
    o4.x = dx * rs * gg.x + bb.x;
    o4.y = dy * rs * gg.y + bb.y;
    o4.z = dz * rs * gg.z + bb.z;
    o4.w = dw * rs * gg.w + bb.w;
    *(float4*)&out[(size_t)wid * D + c] = o4;
}

// ---------------- launch ---------------------------------------------------
static const int EDGE_SMEM = (128 * 136 + 128 * 128 + 128 * 16 + 128) * 4 + 256 * 4;

extern "C" void kernel_launch(void* const* d_in, const int* in_sizes, int n_in,
                              void* d_out, int out_size)
{
    const float* x     = (const float*)d_in[0];
    const int*   ei    = (const int*)  d_in[1];
    const float* ea    = (const float*)d_in[2];
    // d_in[3] = batch (unused)
    const float* W_l   = (const float*)d_in[4];
    const float* b_l   = (const float*)d_in[5];
    const float* W_r   = (const float*)d_in[6];
    const float* b_r   = (const float*)d_in[7];
    const float* W_e   = (const float*)d_in[8];
    const float* att   = (const float*)d_in[9];
    const float* b_att = (const float*)d_in[10];
    const float* W1    = (const float*)d_in[11];
    const float* b1    = (const float*)d_in[12];
    const float* W2    = (const float*)d_in[13];
    const float* b2    = (const float*)d_in[14];
    const float* g1    = (const float*)d_in[15];
    const float* be1   = (const float*)d_in[16];
    const float* g2    = (const float*)d_in[17];
    const float* be2   = (const float*)d_in[18];

    int N = in_sizes[0] / D;
    int E = in_sizes[1] / 2;
    const int* srcA = ei;
    const int* dstA = ei + E;

    // scratch pointers
    float *p_xl, *p_xr, *p_logits, *p_agg, *p_h, *p_f1, *p_f2;
    int *p_deg, *p_rp, *p_cur, *p_bs, *p_eid, *p_srcp;
    cudaGetSymbolAddress((void**)&p_xl, g_xl);
    cudaGetSymbolAddress((void**)&p_xr, g_xr);
    cudaGetSymbolAddress((void**)&p_logits, g_logits);
    cudaGetSymbolAddress((void**)&p_agg, g_agg);
    cudaGetSymbolAddress((void**)&p_h, g_h);
    cudaGetSymbolAddress((void**)&p_f1, g_ffn1);
    cudaGetSymbolAddress((void**)&p_f2, g_f2);
    cudaGetSymbolAddress((void**)&p_deg, g_deg);
    cudaGetSymbolAddress((void**)&p_rp, g_rowptr);
    cudaGetSymbolAddress((void**)&p_cur, g_cursor);
    cudaGetSymbolAddress((void**)&p_bs, g_bsum);
    cudaGetSymbolAddress((void**)&p_eid, g_eid);
    cudaGetSymbolAddress((void**)&p_srcp, g_srcp);

    cudaFuncSetAttribute(edge_logits_kernel,
                         cudaFuncAttributeMaxDynamicSharedMemorySize, EDGE_SMEM);

    // 1) CSR build (dst-sorted)
    int nb = (N + 1023) / 1024;
    k_zero_deg<<<(N + 1023) / 1024, 1024>>>(p_deg, N);
    k_count<<<(E + 255) / 256, 256>>>(dstA, p_deg, E);
    k_scan1<<<nb, 1024>>>(p_deg, p_rp, p_bs, N);
    k_scan2<<<1, 32>>>(p_bs, nb);
    k_scan3<<<nb, 1024>>>(p_deg, p_rp, p_cur, p_bs, N);
    k_fill<<<(E + 255) / 256, 256>>>(srcA, dstA, p_cur, p_eid, p_srcp, E);

    // 2) node transforms
    dim3 gN(1, (N + 127) / 128);
    sgemm_kernel<<<gN, 256>>>(x, W_l, b_l, p_xl, N, 128, 128, 0);
    sgemm_kernel<<<gN, 256>>>(x, W_r, b_r, p_xr, N, 128, 128, 0);

    // 3) fused edge GEMM -> logits
    edge_logits_kernel<<<(E + EPB - 1) / EPB, 256, EDGE_SMEM>>>(
        ea, srcA, dstA, W_e, att, p_xl, p_xr, p_logits, E);

    // 4) per-node softmax + aggregation
    node_attn_kernel<<<(N + 7) / 8, 256>>>(p_rp, p_eid, p_srcp, p_logits, p_xl, p_agg, N);

    // 5) h = LN(x + agg + b_att)
    ln_kernel<<<(N + 7) / 8, 256>>>(x, p_agg, b_att, g1, be1, p_h, N, 1);

    // 6) FFN
    dim3 gF1(4, (N + 127) / 128);
    sgemm_kernel<<<gF1, 256>>>(p_h, W1, b1, p_f1, N, 512, 128, 1);
    dim3 gF2(1, (N + 127) / 128);
    sgemm_kernel<<<gF2, 256>>>(p_f1, W2, b2, p_f2, N, 128, 512, 0);

    // 7) out = LN(h + ffn)
    ln_kernel<<<(N + 7) / 8, 256>>>(p_h, p_f2, nullptr, g2, be2, (float*)d_out, N, 0);
}

// round 6
// speedup vs baseline: 2.5358x; 2.5358x over previous
#include <cuda_runtime.h>
#include <math.h>
#include <stdint.h>

#define D 128
#define HH 8
#define NEG 0.2f
#define LNEPS 1e-5f

#define MAXN 50176
#define MAXE 800256

// ---------------- scratch (static device allocations; no cudaMalloc) -------
__device__ float g_xl[(size_t)MAXN * D];
__device__ float g_xr[(size_t)MAXN * D];
__device__ float g_logits[(size_t)MAXE * HH];
__device__ float g_agg[(size_t)MAXN * D];
__device__ float g_h[(size_t)MAXN * D];
__device__ float g_ffn1[(size_t)MAXN * 4 * D];
__device__ float g_f2[(size_t)MAXN * D];
__device__ float g_wT[262144];          // WlT,WrT,WeT (16K ea) + W1T,W2T (64K ea)
__device__ int   g_deg[MAXN];
__device__ int   g_rowptr[MAXN + 1];
__device__ int   g_cursor[MAXN];
__device__ int   g_bsum[256];
__device__ int   g_eid[MAXE];
__device__ int   g_srcp[MAXE];

// ---------------- TF32 helpers ---------------------------------------------
// NOTE: cvt.rna.tf32.f32 destination is a .b32 register ("=r", NOT "=f").
__device__ __forceinline__ uint32_t tf32r(float x) {
    uint32_t r; asm("cvt.rna.tf32.f32 %0, %1;" : "=r"(r) : "f"(x)); return r;
}
__device__ __forceinline__ void mma_tf32(float* d, const uint32_t* a, const uint32_t* b) {
    asm volatile(
        "mma.sync.aligned.m16n8k8.row.col.f32.tf32.tf32.f32 "
        "{%0,%1,%2,%3}, {%4,%5,%6,%7}, {%8,%9}, {%0,%1,%2,%3};"
        : "+f"(d[0]), "+f"(d[1]), "+f"(d[2]), "+f"(d[3])
        : "r"(a[0]), "r"(a[1]), "r"(a[2]), "r"(a[3]), "r"(b[0]), "r"(b[1]));
}

#define SA 20           // smem tile stride in words (conflict-free frag loads)
#define TILE_WORDS (128 * SA)   // 2560 words = 10240 B per tile

// ---------------- CSR build ------------------------------------------------
__global__ void k_zero_deg(int* deg, int N) {
    int i = blockIdx.x * blockDim.x + threadIdx.x;
    if (i < N) deg[i] = 0;
}
__global__ void k_count(const int* __restrict__ dst, int* deg, int E) {
    int e = blockIdx.x * blockDim.x + threadIdx.x;
    if (e < E) atomicAdd(&deg[dst[e]], 1);
}
__global__ void k_scan1(const int* __restrict__ deg, int* rowptr, int* bsum, int N) {
    __shared__ int sh[1024];
    int t = threadIdx.x;
    int i = blockIdx.x * 1024 + t;
    int v = (i < N) ? deg[i] : 0;
    sh[t] = v;
    __syncthreads();
    for (int off = 1; off < 1024; off <<= 1) {
        int add = (t >= off) ? sh[t - off] : 0;
        __syncthreads();
        sh[t] += add;
        __syncthreads();
    }
    if (i < N) rowptr[i + 1] = sh[t];
    if (t == 1023) bsum[blockIdx.x] = sh[1023];
}
__global__ void k_scan2(int* bsum, int nb) {
    if (threadIdx.x == 0 && blockIdx.x == 0) {
        int run = 0;
        for (int b = 0; b < nb; b++) { int v = bsum[b]; bsum[b] = run; run += v; }
    }
}
__global__ void k_scan3(const int* __restrict__ deg, int* rowptr, int* cursor,
                        const int* __restrict__ bsum, int N) {
    int t = threadIdx.x;
    int i = blockIdx.x * 1024 + t;
    if (i < N) {
        int v = rowptr[i + 1] + bsum[blockIdx.x];
        rowptr[i + 1] = v;
        cursor[i] = v - deg[i];
    }
    if (i == 0) rowptr[0] = 0;
}
__global__ void k_fill(const int* __restrict__ src, const int* __restrict__ dst,
                       int* cursor, int* eid, int* srcp, int E) {
    int e = blockIdx.x * blockDim.x + threadIdx.x;
    if (e < E) {
        int d = dst[e];
        int p = atomicAdd(&cursor[d], 1);
        eid[p]  = e;
        srcp[p] = src[e];
    }
}

// ---------------- weight transpose: out[n*K+k] = in[k*Nc+n] ----------------
__global__ void k_transpose(const float* __restrict__ in, float* __restrict__ out,
                            int K, int Nc) {
    int idx = blockIdx.x * 256 + threadIdx.x;
    if (idx < K * Nc) {
        int k = idx / Nc, n = idx % Nc;
        out[(size_t)n * K + k] = in[idx];
    }
}

// ---------------- generic TF32 mma.sync GEMM -------------------------------
// C[M,Nc] = act(A[M,K] @ (BT[Nc,K])^T + bias). 128x128 tiles, BK=16,
// 256 threads = 8 warps (4m x 2n), warp tile 32x64. act: 0=none, 1=GELU.
__global__ void __launch_bounds__(256) gemm_tc(
    const float* __restrict__ A, const float* __restrict__ BT,
    const float* __restrict__ bias, float* __restrict__ C,
    int M, int Nc, int K, int act)
{
    __shared__ uint32_t sA[2][TILE_WORDS];
    __shared__ uint32_t sB[2][TILE_WORDS];
    __shared__ float sbias[128];

    const int t = threadIdx.x, wid = t >> 5, lane = t & 31;
    const int g = lane >> 2, t4 = lane & 3;
    const int wm = wid >> 1, wn = wid & 1;
    const int m0 = blockIdx.y * 128, n0 = blockIdx.x * 128;

    if (t < 128) sbias[t] = bias[n0 + t];

    float dc[16][4];
#pragma unroll
    for (int i = 0; i < 16; i++)
#pragma unroll
        for (int j = 0; j < 4; j++) dc[i][j] = 0.f;

    const int NC = K >> 4;
    const int row0 = t >> 2,         q0 = t & 3;       // ids 0..255
    const int row1 = (t + 256) >> 2, q1 = t & 3;       // ids 256..511

    float4 pA0, pA1, pB0, pB1;
    auto fetch = [&](int c) {
        const float* Ap = A  + (size_t)m0 * K + c * 16;
        const float* Bp = BT + (size_t)n0 * K + c * 16;
        pA0 = (m0 + row0 < M) ? *(const float4*)(Ap + (size_t)row0 * K + q0 * 4)
                              : make_float4(0.f, 0.f, 0.f, 0.f);
        pA1 = (m0 + row1 < M) ? *(const float4*)(Ap + (size_t)row1 * K + q1 * 4)
                              : make_float4(0.f, 0.f, 0.f, 0.f);
        pB0 = *(const float4*)(Bp + (size_t)row0 * K + q0 * 4);
        pB1 = *(const float4*)(Bp + (size_t)row1 * K + q1 * 4);
    };
    auto stage = [&](int b) {
        uint4 u;
        u = make_uint4(tf32r(pA0.x), tf32r(pA0.y), tf32r(pA0.z), tf32r(pA0.w));
        *(uint4*)&sA[b][row0 * SA + q0 * 4] = u;
        u = make_uint4(tf32r(pA1.x), tf32r(pA1.y), tf32r(pA1.z), tf32r(pA1.w));
        *(uint4*)&sA[b][row1 * SA + q1 * 4] = u;
        u = make_uint4(tf32r(pB0.x), tf32r(pB0.y), tf32r(pB0.z), tf32r(pB0.w));
        *(uint4*)&sB[b][row0 * SA + q0 * 4] = u;
        u = make_uint4(tf32r(pB1.x), tf32r(pB1.y), tf32r(pB1.z), tf32r(pB1.w));
        *(uint4*)&sB[b][row1 * SA + q1 * 4] = u;
    };

    fetch(0);
    stage(0);
    __syncthreads();

    int buf = 0;
    for (int c = 0; c < NC; c++) {
        if (c + 1 < NC) fetch(c + 1);
#pragma unroll
        for (int ks = 0; ks < 2; ks++) {
            int k = ks * 8;
            uint32_t af[2][4], bf[8][2];
#pragma unroll
            for (int i = 0; i < 2; i++) {
                int rb = wm * 32 + i * 16;
                af[i][0] = sA[buf][(rb + g)     * SA + k + t4];
                af[i][1] = sA[buf][(rb + g + 8) * SA + k + t4];
                af[i][2] = sA[buf][(rb + g)     * SA + k + t4 + 4];
                af[i][3] = sA[buf][(rb + g + 8) * SA + k + t4 + 4];
            }
#pragma unroll
            for (int j = 0; j < 8; j++) {
                int cb = wn * 64 + j * 8;
                bf[j][0] = sB[buf][(cb + g) * SA + k + t4];
                bf[j][1] = sB[buf][(cb + g) * SA + k + t4 + 4];
            }
#pragma unroll
            for (int i = 0; i < 2; i++)
#pragma unroll
                for (int j = 0; j < 8; j++)
                    mma_tf32(dc[i * 8 + j], af[i], bf[j]);
        }
        if (c + 1 < NC) {
            stage(1 - buf);
            __syncthreads();
            buf ^= 1;
        }
    }

    // epilogue
#pragma unroll
    for (int i = 0; i < 2; i++) {
        int r0 = m0 + wm * 32 + i * 16 + g;
        int r1 = r0 + 8;
#pragma unroll
        for (int j = 0; j < 8; j++) {
            int cl = wn * 64 + j * 8 + 2 * t4;   // block-local col
            float* cf = dc[i * 8 + j];
            float b0 = sbias[cl], b1 = sbias[cl + 1];
            float v0 = cf[0] + b0, v1 = cf[1] + b1;
            float v2 = cf[2] + b0, v3 = cf[3] + b1;
            if (act) {
                v0 = 0.5f * v0 * (1.0f + erff(v0 * 0.70710678118654752f));
                v1 = 0.5f * v1 * (1.0f + erff(v1 * 0.70710678118654752f));
                v2 = 0.5f * v2 * (1.0f + erff(v2 * 0.70710678118654752f));
                v3 = 0.5f * v3 * (1.0f + erff(v3 * 0.70710678118654752f));
            }
            if (r0 < M) *(float2*)&C[(size_t)r0 * Nc + n0 + cl] = make_float2(v0, v1);
            if (r1 < M) *(float2*)&C[(size_t)r1 * Nc + n0 + cl] = make_float2(v2, v3);
        }
    }
}

// ---------------- fused edge kernel: logits[e,h] ---------------------------
// ee = EA_tile @ We (TF32 mma), epilogue: +xl[src]+xr[dst], leaky, att-dot.
// Dynamic smem layout:
//   [0, 67584)      sxsum[128][132]  (mainloop reuses [0,40960) for A/B tiles)
//   [67584, 71680)  part[128][8]
//   [71680, 72192)  satt[128]
//   [72192, 72704)  ssrc[128]
//   [72704, 73216)  sdst[128]
#define ESM_PART 67584
#define ESM_ATT  71680
#define ESM_SRC  72192
#define ESM_DST  72704
#define EDGE_SMEM 73216
#define SXS 132

__global__ void __launch_bounds__(256) edge_logits_tc(
    const float* __restrict__ EA, const int* __restrict__ srcA,
    const int* __restrict__ dstA, const float* __restrict__ WeT,
    const float* __restrict__ att, const float* __restrict__ xl,
    const float* __restrict__ xr, float* __restrict__ logits, int E)
{
    extern __shared__ char smem[];
    float* sx   = (float*)smem;
    float* part = (float*)(smem + ESM_PART);
    float* satt = (float*)(smem + ESM_ATT);
    int*   ssrc = (int*)(smem + ESM_SRC);
    int*   sdst = (int*)(smem + ESM_DST);

    const int t = threadIdx.x, wid = t >> 5, lane = t & 31;
    const int g = lane >> 2, t4 = lane & 3;
    const int wm = wid >> 1, wn = wid & 1;
    const int e0 = blockIdx.x * 128;

    if (t < 128) {
        satt[t] = att[t];
        ssrc[t] = srcA[e0 + t];
        sdst[t] = dstA[e0 + t];
    }

    float dc[16][4];
#pragma unroll
    for (int i = 0; i < 16; i++)
#pragma unroll
        for (int j = 0; j < 4; j++) dc[i][j] = 0.f;

    const int row0 = t >> 2,         q0 = t & 3;
    const int row1 = (t + 256) >> 2, q1 = t & 3;
    float4 pA0, pA1, pB0, pB1;
    auto fetch = [&](int c) {
        const float* Ap = EA  + (size_t)e0 * 128 + c * 16;
        const float* Bp = WeT + c * 16;
        pA0 = *(const float4*)(Ap + (size_t)row0 * 128 + q0 * 4);
        pA1 = *(const float4*)(Ap + (size_t)row1 * 128 + q1 * 4);
        pB0 = *(const float4*)(Bp + (size_t)row0 * 128 + q0 * 4);
        pB1 = *(const float4*)(Bp + (size_t)row1 * 128 + q1 * 4);
    };
    auto stage = [&](int b) {
        uint32_t* sAw = (uint32_t*)(smem + b * 10240);
        uint32_t* sBw = (uint32_t*)(smem + 20480 + b * 10240);
        uint4 u;
        u = make_uint4(tf32r(pA0.x), tf32r(pA0.y), tf32r(pA0.z), tf32r(pA0.w));
        *(uint4*)&sAw[row0 * SA + q0 * 4] = u;
        u = make_uint4(tf32r(pA1.x), tf32r(pA1.y), tf32r(pA1.z), tf32r(pA1.w));
        *(uint4*)&sAw[row1 * SA + q1 * 4] = u;
        u = make_uint4(tf32r(pB0.x), tf32r(pB0.y), tf32r(pB0.z), tf32r(pB0.w));
        *(uint4*)&sBw[row0 * SA + q0 * 4] = u;
        u = make_uint4(tf32r(pB1.x), tf32r(pB1.y), tf32r(pB1.z), tf32r(pB1.w));
        *(uint4*)&sBw[row1 * SA + q1 * 4] = u;
    };

    fetch(0);
    stage(0);
    __syncthreads();

    int buf = 0;
    for (int c = 0; c < 8; c++) {
        if (c + 1 < 8) fetch(c + 1);
        uint32_t* sAw = (uint32_t*)(smem + buf * 10240);
        uint32_t* sBw = (uint32_t*)(smem + 20480 + buf * 10240);
#pragma unroll
        for (int ks = 0; ks < 2; ks++) {
            int k = ks * 8;
            uint32_t af[2][4], bf[8][2];
#pragma unroll
            for (int i = 0; i < 2; i++) {
                int rb = wm * 32 + i * 16;
                af[i][0] = sAw[(rb + g)     * SA + k + t4];
                af[i][1] = sAw[(rb + g + 8) * SA + k + t4];
                af[i][2] = sAw[(rb + g)     * SA + k + t4 + 4];
                af[i][3] = sAw[(rb + g + 8) * SA + k + t4 + 4];
            }
#pragma unroll
            for (int j = 0; j < 8; j++) {
                int cb = wn * 64 + j * 8;
                bf[j][0] = sBw[(cb + g) * SA + k + t4];
                bf[j][1] = sBw[(cb + g) * SA + k + t4 + 4];
            }
#pragma unroll
            for (int i = 0; i < 2; i++)
#pragma unroll
                for (int j = 0; j < 8; j++)
                    mma_tf32(dc[i * 8 + j], af[i], bf[j]);
        }
        if (c + 1 < 8) {
            stage(1 - buf);
            __syncthreads();
            buf ^= 1;
        }
    }
    __syncthreads();   // tiles dead; reuse region for sxsum

    // stage sxsum[row][col] = xl[src[row]][col] + xr[dst[row]][col]
    for (int idx = t; idx < 128 * 32; idx += 256) {
        int row = idx >> 5, q = idx & 31;
        float4 a4 = *(const float4*)&xl[(size_t)ssrc[row] * D + q * 4];
        float4 b4 = *(const float4*)&xr[(size_t)sdst[row] * D + q * 4];
        float4 s4 = make_float4(a4.x + b4.x, a4.y + b4.y, a4.z + b4.z, a4.w + b4.w);
        *(float4*)&sx[row * SXS + q * 4] = s4;
    }
    __syncthreads();

    // per-fragment epilogue: leaky-relu + att-dot, accumulate per (row, head)
    float hsum[4][4];
#pragma unroll
    for (int i = 0; i < 4; i++)
#pragma unroll
        for (int j = 0; j < 4; j++) hsum[i][j] = 0.f;

#pragma unroll
    for (int i = 0; i < 2; i++) {
        int r0 = wm * 32 + i * 16 + g;
        int r1 = r0 + 8;
#pragma unroll
        for (int j = 0; j < 8; j++) {
            int cl = wn * 64 + j * 8 + 2 * t4;
            int hh = (j * 8 + 2 * t4) >> 4;          // head 0..3 within warp's 4
            float* cf = dc[i * 8 + j];
            float2 s0 = *(float2*)&sx[r0 * SXS + cl];
            float2 s1 = *(float2*)&sx[r1 * SXS + cl];
            float a0 = satt[cl], a1 = satt[cl + 1];
            float v;
            v = cf[0] + s0.x; v = (v > 0.f) ? v : NEG * v; hsum[i * 2 + 0][hh] += v * a0;
            v = cf[1] + s0.y; v = (v > 0.f) ? v : NEG * v; hsum[i * 2 + 0][hh] += v * a1;
            v = cf[2] + s1.x; v = (v > 0.f) ? v : NEG * v; hsum[i * 2 + 1][hh] += v * a0;
            v = cf[3] + s1.y; v = (v > 0.f) ? v : NEG * v; hsum[i * 2 + 1][hh] += v * a1;
        }
    }
    // reduce across the 4 lanes (t4) that share each row
#pragma unroll
    for (int i = 0; i < 4; i++)
#pragma unroll
        for (int j = 0; j < 4; j++) {
            float v = hsum[i][j];
            v += __shfl_xor_sync(0xffffffffu, v, 1);
            v += __shfl_xor_sync(0xffffffffu, v, 2);
            hsum[i][j] = v;
        }
    if (t4 == 0) {
#pragma unroll
        for (int i = 0; i < 2; i++) {
            int r0 = wm * 32 + i * 16 + g;
#pragma unroll
            for (int hh = 0; hh < 4; hh++) {
                part[r0 * 8 + wn * 4 + hh]       = hsum[i * 2 + 0][hh];
                part[(r0 + 8) * 8 + wn * 4 + hh] = hsum[i * 2 + 1][hh];
            }
        }
    }
    __syncthreads();
    if (t < 128) {
        int e = e0 + t;
        *(float4*)&logits[(size_t)e * HH]     = *(float4*)&part[t * 8];
        *(float4*)&logits[(size_t)e * HH + 4] = *(float4*)&part[t * 8 + 4];
    }
}

// ---------------- per-node softmax + aggregation (warp per node) -----------
__global__ void node_attn_kernel(const int* __restrict__ rowptr,
                                 const int* __restrict__ eid,
                                 const int* __restrict__ srcp,
                                 const float* __restrict__ logits,
                                 const float* __restrict__ xl,
                                 float* __restrict__ agg, int N)
{
    int wid  = (blockIdx.x * blockDim.x + threadIdx.x) >> 5;
    int lane = threadIdx.x & 31;
    if (wid >= N) return;
    int n   = wid;
    int beg = rowptr[n], end = rowptr[n + 1];

    int h = lane & 7, rep = lane >> 3;
    float mx = -1e30f;
    for (int i = beg + rep; i < end; i += 4)
        mx = fmaxf(mx, logits[(size_t)eid[i] * HH + h]);
    mx = fmaxf(mx, __shfl_xor_sync(0xffffffffu, mx, 8));
    mx = fmaxf(mx, __shfl_xor_sync(0xffffffffu, mx, 16));
    float sum = 0.f;
    for (int i = beg + rep; i < end; i += 4)
        sum += expf(logits[(size_t)eid[i] * HH + h] - mx);
    sum += __shfl_xor_sync(0xffffffffu, sum, 8);
    sum += __shfl_xor_sync(0xffffffffu, sum, 16);
    float inv = 1.f / (sum + 1e-16f);

    int h2 = lane >> 2;
    float mxh  = __shfl_sync(0xffffffffu, mx,  h2);
    float invh = __shfl_sync(0xffffffffu, inv, h2);
    int off = lane * 4;

    float4 acc = make_float4(0.f, 0.f, 0.f, 0.f);
    for (int i = beg; i < end; i++) {
        int e  = eid[i];
        int sN = srcp[i];
        float a = expf(logits[(size_t)e * HH + h2] - mxh) * invh;
        float4 v = *(const float4*)&xl[(size_t)sN * D + off];
        acc.x += a * v.x; acc.y += a * v.y; acc.z += a * v.z; acc.w += a * v.w;
    }
    *(float4*)&agg[(size_t)n * D + off] = acc;
}

// ---------------- LayerNorm over D=128 (warp per row) ----------------------
__global__ void ln_kernel(const float* __restrict__ a, const float* __restrict__ b,
                          const float* __restrict__ extra_bias,
                          const float* __restrict__ g, const float* __restrict__ be,
                          float* __restrict__ out, int N, int has_extra)
{
    int wid  = (blockIdx.x * blockDim.x + threadIdx.x) >> 5;
    int lane = threadIdx.x & 31;
    if (wid >= N) return;
    int c = lane * 4;
    float4 va = *(const float4*)&a[(size_t)wid * D + c];
    float4 vb = *(const float4*)&b[(size_t)wid * D + c];
    float4 v = make_float4(va.x + vb.x, va.y + vb.y, va.z + vb.z, va.w + vb.w);
    if (has_extra) {
        float4 ex = *(const float4*)&extra_bias[c];
        v.x += ex.x; v.y += ex.y; v.z += ex.z; v.w += ex.w;
    }
    float s = v.x + v.y + v.z + v.w;
#pragma unroll
    for (int o = 1; o < 32; o <<= 1) s += __shfl_xor_sync(0xffffffffu, s, o);
    float mu = s * (1.f / 128.f);
    float dx = v.x - mu, dy = v.y - mu, dz = v.z - mu, dw = v.w - mu;
    float q = dx * dx + dy * dy + dz * dz + dw * dw;
#pragma unroll
    for (int o = 1; o < 32; o <<= 1) q += __shfl_xor_sync(0xffffffffu, q, o);
    float rs = rsqrtf(q * (1.f / 128.f) + LNEPS);
    float4 gg = *(const float4*)&g[c];
    float4 bb = *(const float4*)&be[c];
    float4 o4;
    o4.x = dx * rs * gg.x + bb.x;
    o4.y = dy * rs * gg.y + bb.y;
    o4.z = dz * rs * gg.z + bb.z;
    o4.w = dw * rs * gg.w + bb.w;
    *(float4*)&out[(size_t)wid * D + c] = o4;
}

// ---------------- launch ---------------------------------------------------
extern "C" void kernel_launch(void* const* d_in, const int* in_sizes, int n_in,
                              void* d_out, int out_size)
{
    const float* x     = (const float*)d_in[0];
    const int*   ei    = (const int*)  d_in[1];
    const float* ea    = (const float*)d_in[2];
    const float* W_l   = (const float*)d_in[4];
    const float* b_l   = (const float*)d_in[5];
    const float* W_r   = (const float*)d_in[6];
    const float* b_r   = (const float*)d_in[7];
    const float* W_e   = (const float*)d_in[8];
    const float* att   = (const float*)d_in[9];
    const float* b_att = (const float*)d_in[10];
    const float* W1    = (const float*)d_in[11];
    const float* b1    = (const float*)d_in[12];
    const float* W2    = (const float*)d_in[13];
    const float* b2    = (const float*)d_in[14];
    const float* g1    = (const float*)d_in[15];
    const float* be1   = (const float*)d_in[16];
    const float* g2    = (const float*)d_in[17];
    const float* be2   = (const float*)d_in[18];

    int N = in_sizes[0] / D;
    int E = in_sizes[1] / 2;
    const int* srcA = ei;
    const int* dstA = ei + E;

    float *p_xl, *p_xr, *p_logits, *p_agg, *p_h, *p_f1, *p_f2, *p_wT;
    int *p_deg, *p_rp, *p_cur, *p_bs, *p_eid, *p_srcp;
    cudaGetSymbolAddress((void**)&p_xl, g_xl);
    cudaGetSymbolAddress((void**)&p_xr, g_xr);
    cudaGetSymbolAddress((void**)&p_logits, g_logits);
    cudaGetSymbolAddress((void**)&p_agg, g_agg);
    cudaGetSymbolAddress((void**)&p_h, g_h);
    cudaGetSymbolAddress((void**)&p_f1, g_ffn1);
    cudaGetSymbolAddress((void**)&p_f2, g_f2);
    cudaGetSymbolAddress((void**)&p_wT, g_wT);
    cudaGetSymbolAddress((void**)&p_deg, g_deg);
    cudaGetSymbolAddress((void**)&p_rp, g_rowptr);
    cudaGetSymbolAddress((void**)&p_cur, g_cursor);
    cudaGetSymbolAddress((void**)&p_bs, g_bsum);
    cudaGetSymbolAddress((void**)&p_eid, g_eid);
    cudaGetSymbolAddress((void**)&p_srcp, g_srcp);

    float* WlT = p_wT;
    float* WrT = p_wT + 16384;
    float* WeT = p_wT + 32768;
    float* W1T = p_wT + 49152;
    float* W2T = p_wT + 114688;

    cudaFuncSetAttribute(edge_logits_tc,
                         cudaFuncAttributeMaxDynamicSharedMemorySize, EDGE_SMEM);

    // 0) weight transposes (n-major for mma B operand)
    k_transpose<<<64, 256>>>(W_l, WlT, 128, 128);
    k_transpose<<<64, 256>>>(W_r, WrT, 128, 128);
    k_transpose<<<64, 256>>>(W_e, WeT, 128, 128);
    k_transpose<<<256, 256>>>(W1, W1T, 128, 512);
    k_transpose<<<256, 256>>>(W2, W2T, 512, 128);

    // 1) CSR build (dst-sorted)
    int nb = (N + 1023) / 1024;
    k_zero_deg<<<(N + 1023) / 1024, 1024>>>(p_deg, N);
    k_count<<<(E + 255) / 256, 256>>>(dstA, p_deg, E);
    k_scan1<<<nb, 1024>>>(p_deg, p_rp, p_bs, N);
    k_scan2<<<1, 32>>>(p_bs, nb);
    k_scan3<<<nb, 1024>>>(p_deg, p_rp, p_cur, p_bs, N);
    k_fill<<<(E + 255) / 256, 256>>>(srcA, dstA, p_cur, p_eid, p_srcp, E);

    // 2) node transforms (TF32 tensor cores)
    int mt = (N + 127) / 128;
    gemm_tc<<<dim3(1, mt), 256>>>(x, WlT, b_l, p_xl, N, 128, 128, 0);
    gemm_tc<<<dim3(1, mt), 256>>>(x, WrT, b_r, p_xr, N, 128, 128, 0);

    // 3) fused edge GEMM -> logits
    edge_logits_tc<<<E / 128, 256, EDGE_SMEM>>>(
        ea, srcA, dstA, WeT, att, p_xl, p_xr, p_logits, E);

    // 4) per-node softmax + aggregation
    node_attn_kernel<<<(N + 7) / 8, 256>>>(p_rp, p_eid, p_srcp, p_logits, p_xl, p_agg, N);

    // 5) h = LN(x + agg + b_att)
    ln_kernel<<<(N + 7) / 8, 256>>>(x, p_agg, b_att, g1, be1, p_h, N, 1);

    // 6) FFN
    gemm_tc<<<dim3(4, mt), 256>>>(p_h, W1T, b1, p_f1, N, 512, 128, 1);
    gemm_tc<<<dim3(1, mt), 256>>>(p_f1, W2T, b2, p_f2, N, 128, 512, 0);

    // 7) out = LN(h + ffn)
    ln_kernel<<<(N + 7) / 8, 256>>>(p_h, p_f2, nullptr, g2, be2, (float*)d_out, N, 0);
}